// round 1
// baseline (speedup 1.0000x reference)
#include <cuda_runtime.h>
#include <math.h>

#define NN 50000
#define EE 800000
#define INC 64
#define HC 128
#define C1N 64
#define C2N 16
#define LN_EPS 1e-5f
#define THRESH1 (1.0f/63.0f)

// ---------------- device scratch (no allocation allowed) ----------------
__device__ __align__(16) float d_agg[NN*INC];     // sum_{row->col} x_drop[row]
__device__ __align__(16) float d_x1[NN*HC];       // relu(graph_conv1)
__device__ __align__(16) float d_s[NN*C1N];       // softmax(s1)
__device__ __align__(16) float d_As[NN*C1N];      // A @ s
__device__ __align__(16) float d_deg[NN];
__device__ __align__(16) float d_pooled[C1N*256]; // [a][0:128]=pooled_x [128:192]=pooled_adj [192:256]=sTs
__device__ float d_den;

__device__ __forceinline__ void red_add4(float* addr, float4 v) {
    asm volatile("red.global.add.v4.f32 [%0], {%1,%2,%3,%4};"
                 :: "l"(addr), "f"(v.x), "f"(v.y), "f"(v.z), "f"(v.w) : "memory");
}

// ---------------- zero scratch ----------------
__global__ void kzero() {
    int i0 = blockIdx.x*blockDim.x + threadIdx.x, st = gridDim.x*blockDim.x;
    for (int i = i0; i < NN*INC; i += st) { d_agg[i] = 0.f; d_As[i] = 0.f; }
    for (int i = i0; i < NN;     i += st) d_deg[i] = 0.f;
    for (int i = i0; i < C1N*256; i += st) d_pooled[i] = 0.f;
    if (i0 == 0) d_den = 0.f;
}

// ---------------- scatter 1: agg[col] += x[row]*dm[row]; deg[row] += 1 ----------------
__global__ void kscatter1(const float* __restrict__ x, const float* __restrict__ dm,
                          const int* __restrict__ row, const int* __restrict__ col) {
    int i0 = blockIdx.x*blockDim.x + threadIdx.x, st = gridDim.x*blockDim.x;
    for (int i = i0; i < EE*16; i += st) {
        int e = i >> 4, c = i & 15;
        int r = row[e];
        if (c == 0) atomicAdd(&d_deg[r], 1.0f);
        float m = dm[r];
        if (m != 0.0f) {
            int d = col[e];
            float4 v = ((const float4*)(x + (size_t)r*INC))[c];
            v.x *= m; v.y *= m; v.z *= m; v.w *= m;
            red_add4((float*)(((float4*)(d_agg + (size_t)d*INC)) + c), v);
        }
    }
}

// ---------------- scatter 2: A_s[row] += s[col] ----------------
__global__ void kscatter2(const int* __restrict__ row, const int* __restrict__ col) {
    int i0 = blockIdx.x*blockDim.x + threadIdx.x, st = gridDim.x*blockDim.x;
    for (int i = i0; i < EE*16; i += st) {
        int e = i >> 4, c = i & 15;
        int srcn = col[e];
        int dstn = row[e];
        float4 v = ((const float4*)(d_s + (size_t)srcn*C1N))[c];
        red_add4((float*)(((float4*)(d_As + (size_t)dstn*C1N)) + c), v);
    }
}

// ---------------- fused per-node: x1 = relu(conv), s1 = LN(x1@pW1^T+pb1), ls1/softmax ----------------
// dynamic smem layout (floats):
//  Wt[128*129] transposed cat weights ([k][h], k<64 rel, k>=64 root)
//  pWt[128*65] transposed pW1 ([h][c])
//  b1s[128] pb1s[64] g1s[64] be1s[64] aggs[64] xds[64] x1s[128] redb[8]
#define K3_SMEM_FLOATS (128*129 + 128*65 + 128 + 64 + 64 + 64 + 64 + 64 + 128 + 8)
#define K3_SMEM_BYTES  (K3_SMEM_FLOATS*4)

__global__ void __launch_bounds__(128, 2) k3(
    const float* __restrict__ x, const float* __restrict__ dm,
    const float* __restrict__ W1rel, const float* __restrict__ b1, const float* __restrict__ W1root,
    const float* __restrict__ pW1, const float* __restrict__ pb1,
    const float* __restrict__ g1, const float* __restrict__ be1,
    float* __restrict__ ls1out) {
    extern __shared__ float sm[];
    float* Wt   = sm;               // 16512
    float* pWt  = Wt + 128*129;     // 8320
    float* b1s  = pWt + 128*65;     // 128
    float* pb1s = b1s + 128;        // 64
    float* g1s  = pb1s + 64;        // 64
    float* be1s = g1s + 64;         // 64
    float* aggs = be1s + 64;        // 64
    float* xds  = aggs + 64;        // 64
    float* x1s  = xds + 64;         // 128
    float* redb = x1s + 128;        // 8

    int t = threadIdx.x;
    // stage weights (transposed, padded -> conflict-free)
    for (int i = t; i < HC*INC; i += 128) {
        int h = i >> 6, k = i & 63;
        Wt[k*129 + h]        = W1rel[i];
        Wt[(k+64)*129 + h]   = W1root[i];
    }
    for (int i = t; i < C1N*HC; i += 128) {
        int c = i >> 7, h = i & 127;
        pWt[h*65 + c] = pW1[i];
    }
    if (t < 128) b1s[t] = b1[t];
    if (t < 64) { pb1s[t] = pb1[t]; g1s[t] = g1[t]; be1s[t] = be1[t]; }
    __syncthreads();

    int lane = t & 31, wid = t >> 5;

    for (int n = blockIdx.x; n < NN; n += gridDim.x) {
        float dmn = dm[n];
        if (t < 64) {
            aggs[t] = d_agg[(size_t)n*INC + t];
            xds[t]  = x[(size_t)n*INC + t] * dmn;
        }
        __syncthreads();

        // phase 1: x1[h=t]
        float a0 = 0.f, a1 = 0.f, a2 = 0.f, a3 = 0.f;
        #pragma unroll
        for (int k = 0; k < 64; k += 4) {
            a0 += aggs[k]   * Wt[k*129 + t];
            a1 += aggs[k+1] * Wt[(k+1)*129 + t];
            a2 += aggs[k+2] * Wt[(k+2)*129 + t];
            a3 += aggs[k+3] * Wt[(k+3)*129 + t];
        }
        #pragma unroll
        for (int k = 0; k < 64; k += 4) {
            a0 += xds[k]   * Wt[(k+64)*129 + t];
            a1 += xds[k+1] * Wt[(k+65)*129 + t];
            a2 += xds[k+2] * Wt[(k+66)*129 + t];
            a3 += xds[k+3] * Wt[(k+67)*129 + t];
        }
        float x1v = fmaxf(a0 + a1 + a2 + a3 + b1s[t], 0.f);
        d_x1[(size_t)n*HC + t] = x1v;
        x1s[t] = x1v;
        __syncthreads();

        // phase 2: s1raw[c=t] for t<64
        float v = 0.f;
        if (t < 64) {
            float c0 = 0.f, c1 = 0.f, c2 = 0.f, c3 = 0.f;
            #pragma unroll
            for (int h = 0; h < 128; h += 4) {
                c0 += x1s[h]   * pWt[h*65 + t];
                c1 += x1s[h+1] * pWt[(h+1)*65 + t];
                c2 += x1s[h+2] * pWt[(h+2)*65 + t];
                c3 += x1s[h+3] * pWt[(h+3)*65 + t];
            }
            v = c0 + c1 + c2 + c3 + pb1s[t];
            // reduce sum & sumsq over the 2 active warps
            float s_ = v, q_ = v*v;
            #pragma unroll
            for (int o = 16; o; o >>= 1) {
                s_ += __shfl_xor_sync(0xffffffffu, s_, o);
                q_ += __shfl_xor_sync(0xffffffffu, q_, o);
            }
            if (lane == 0) { redb[wid] = s_; redb[2 + wid] = q_; }
        }
        __syncthreads();
        float mu  = (redb[0] + redb[1]) * (1.f/64.f);
        float msq = (redb[2] + redb[3]) * (1.f/64.f);
        float rstd = rsqrtf(msq - mu*mu + LN_EPS);
        float nv = 0.f;
        if (t < 64) {
            nv = (v - mu) * rstd * g1s[t] + be1s[t];
            float m_ = nv;
            #pragma unroll
            for (int o = 16; o; o >>= 1) m_ = fmaxf(m_, __shfl_xor_sync(0xffffffffu, m_, o));
            if (lane == 0) redb[4 + wid] = m_;
        }
        __syncthreads();
        float mx = fmaxf(redb[4], redb[5]);
        float ex = 0.f;
        if (t < 64) {
            ex = expf(nv - mx);
            float e_ = ex;
            #pragma unroll
            for (int o = 16; o; o >>= 1) e_ += __shfl_xor_sync(0xffffffffu, e_, o);
            if (lane == 0) redb[6 + wid] = e_;
        }
        __syncthreads();
        float lse = mx + logf(redb[6] + redb[7]);
        if (t < 64) {
            float ls = nv - lse;
            ls1out[(size_t)n*C1N + t] = ls;
            d_s[(size_t)n*C1N + t]    = expf(ls);
        }
        __syncthreads();
    }
}

// ---------------- node reduction: pooled[a][c] = sum_i s[i,a]*V[i,c], den ----------------
__global__ void __launch_bounds__(256, 2) k5() {
    __shared__ float V8[8][256];
    __shared__ float S8[8][64];
    __shared__ float D8[8];
    __shared__ float redw[8];

    float acc[64];
    #pragma unroll
    for (int a = 0; a < 64; a++) acc[a] = 0.f;
    float denAcc = 0.f;

    int t = threadIdx.x;
    int per = (NN + gridDim.x - 1) / gridDim.x;
    int n0 = blockIdx.x * per;
    int n1 = n0 + per; if (n1 > NN) n1 = NN;

    for (int nb = n0; nb < n1; nb += 8) {
        int cnt = n1 - nb; if (cnt > 8) cnt = 8;
        for (int i = t; i < cnt*256; i += 256) {
            int ni = i >> 8, c = i & 255;
            size_t node = (size_t)(nb + ni);
            float val;
            if (c < 128)      val = d_x1[node*HC + c];
            else if (c < 192) val = d_As[node*C1N + (c - 128)];
            else              val = d_s[node*C1N + (c - 192)];
            V8[ni][c] = val;
        }
        for (int i = t; i < cnt*64; i += 256) {
            int ni = i >> 6, a = i & 63;
            S8[ni][a] = d_s[(size_t)(nb + ni)*C1N + a];
        }
        if (t < cnt) D8[t] = d_deg[nb + t];
        __syncthreads();

        for (int ni = 0; ni < cnt; ni++) {
            float v = V8[ni][t];
            #pragma unroll
            for (int a = 0; a < 64; a++) acc[a] += S8[ni][a] * v;
        }
        for (int i = t; i < cnt*64; i += 256) {
            int ni = i >> 6, a = i & 63;
            float sv = S8[ni][a];
            denAcc += D8[ni] * sv * sv;
        }
        __syncthreads();
    }

    #pragma unroll
    for (int a = 0; a < 64; a++) atomicAdd(&d_pooled[a*256 + t], acc[a]);

    // reduce denAcc
    #pragma unroll
    for (int o = 16; o; o >>= 1) denAcc += __shfl_xor_sync(0xffffffffu, denAcc, o);
    if ((t & 31) == 0) redw[t >> 5] = denAcc;
    __syncthreads();
    if (t == 0) {
        float s = 0.f;
        for (int w = 0; w < 8; w++) s += redw[w];
        atomicAdd(&d_den, s);
    }
}

// ---------------- final tiny stage (single block) ----------------
__device__ __forceinline__ float k6_sum(float v, float* redb, float* scal) {
    redb[threadIdx.x] = v;
    __syncthreads();
    if (threadIdx.x == 0) {
        float s = 0.f;
        for (int i = 0; i < 256; i++) s += redb[i];
        scal[0] = s;
    }
    __syncthreads();
    float r = scal[0];
    __syncthreads();
    return r;
}

#define K6_SMEM_FLOATS (8192 + 4096 + 4096 + 4096 + 8192 + 8192 + 1024 + 1024 + 1024 + 256 + 256 + 64 + 64 + 256 + 8)
#define K6_SMEM_BYTES  (K6_SMEM_FLOATS*4)

__global__ void __launch_bounds__(256, 1) k6(
    const float* __restrict__ W2rel, const float* __restrict__ b2, const float* __restrict__ W2root,
    const float* __restrict__ pW2, const float* __restrict__ pb2,
    const float* __restrict__ g2, const float* __restrict__ be2,
    float* __restrict__ out, float* __restrict__ ls2out) {
    extern __shared__ float sm[];
    float* px    = sm;             // 8192  pooled_x [64][128]
    float* paS   = px + 8192;      // 4096  pooled_adj [64][64]
    float* stsS  = paS + 4096;     // 4096
    float* Ms    = stsS + 4096;    // 4096
    float* t1S   = Ms + 4096;      // 8192
    float* x2S   = t1S + 8192;     // 8192
    float* s2raw = x2S + 8192;     // 1024
    float* s2S   = s2raw + 1024;   // 1024
    float* As2   = s2S + 1024;     // 1024
    float* pa2   = As2 + 1024;     // 256
    float* sts2  = pa2 + 256;      // 256
    float* dsi   = sts2 + 256;     // 64
    float* deg2  = dsi + 64;       // 64
    float* redb  = deg2 + 64;      // 256
    float* scal  = redb + 256;     // 8

    int t = threadIdx.x;
    for (int i = t; i < 8192; i += 256) px[i]   = d_pooled[((i >> 7) << 8) + (i & 127)];
    for (int i = t; i < 4096; i += 256) paS[i]  = d_pooled[((i >> 6) << 8) + 128 + (i & 63)];
    for (int i = t; i < 4096; i += 256) stsS[i] = d_pooled[((i >> 6) << 8) + 192 + (i & 63)];
    __syncthreads();

    // mc1
    float tr = k6_sum((t < 64) ? paS[t*64 + t] : 0.f, redb, scal);
    float mc1 = -tr / (d_den + 1e-10f);

    // ortho 1
    float fq = 0.f;
    for (int i = t; i < 4096; i += 256) { float u = stsS[i]; fq += u*u; }
    float norm = sqrtf(k6_sum(fq, redb, scal));
    float oq = 0.f;
    for (int i = t; i < 4096; i += 256) {
        float u = stsS[i] / (norm + 1e-10f) - (((i >> 6) == (i & 63)) ? 0.125f : 0.f);
        oq += u*u;
    }
    float o1 = sqrtf(k6_sum(oq, redb, scal));

    // adj_norm -> M
    if (t < 64) {
        float rs = 0.f;
        for (int b = 0; b < 64; b++) if (b != t) rs += paS[t*64 + b];
        dsi[t] = 1.f / (sqrtf(rs) + 1e-15f);
    }
    __syncthreads();
    for (int i = t; i < 4096; i += 256) {
        int a = i >> 6, b = i & 63;
        float adjn = (a == b) ? 0.f : paS[i] * dsi[a] * dsi[b];
        Ms[i] = (adjn > THRESH1) ? 1.f : 0.f;
    }
    __syncthreads();

    // t1 = M^T @ px
    for (int i = t; i < 8192; i += 256) {
        int a = i >> 7, f = i & 127;
        float acc = 0.f;
        for (int b = 0; b < 64; b++) acc += Ms[b*64 + a] * px[b*128 + f];
        t1S[i] = acc;
    }
    __syncthreads();

    // x2 = relu(t1 @ W2rel^T + b2 + px @ W2root^T)
    for (int i = t; i < 8192; i += 256) {
        int a = i >> 7, h = i & 127;
        float acc = b2[h];
        const float* wr = W2rel + h*128;
        const float* wo = W2root + h*128;
        for (int f = 0; f < 128; f++) acc += t1S[a*128 + f] * wr[f] + px[a*128 + f] * wo[f];
        x2S[i] = fmaxf(acc, 0.f);
    }
    __syncthreads();

    // s2raw = x2 @ pW2^T + pb2
    for (int i = t; i < 1024; i += 256) {
        int a = i >> 4, c = i & 15;
        float acc = pb2[c];
        const float* w = pW2 + c*128;
        for (int h = 0; h < 128; h++) acc += x2S[a*128 + h] * w[h];
        s2raw[i] = acc;
    }
    __syncthreads();

    // LN + log_softmax + softmax per row (64 rows of 16)
    if (t < 64) {
        float mu = 0.f, msq = 0.f;
        for (int c = 0; c < 16; c++) { float u = s2raw[t*16 + c]; mu += u; msq += u*u; }
        mu *= (1.f/16.f); msq *= (1.f/16.f);
        float rstd = rsqrtf(msq - mu*mu + LN_EPS);
        float nv[16]; float mx = -1e30f;
        for (int c = 0; c < 16; c++) {
            nv[c] = (s2raw[t*16 + c] - mu) * rstd * g2[c] + be2[c];
            mx = fmaxf(mx, nv[c]);
        }
        float es = 0.f;
        for (int c = 0; c < 16; c++) es += expf(nv[c] - mx);
        float lse = mx + logf(es);
        for (int c = 0; c < 16; c++) {
            float ls = nv[c] - lse;
            ls2out[t*16 + c] = ls;
            s2S[t*16 + c] = expf(ls);
        }
        float dg = 0.f;
        for (int b = 0; b < 64; b++) dg += Ms[t*64 + b];
        deg2[t] = dg;
    }
    __syncthreads();

    // A_s2 = M @ s2
    for (int i = t; i < 1024; i += 256) {
        int a = i >> 4, c = i & 15;
        float acc = 0.f;
        for (int b = 0; b < 64; b++) acc += Ms[a*64 + b] * s2S[b*16 + c];
        As2[i] = acc;
    }
    __syncthreads();

    // pa2 = s2^T @ As2 ; sts2 = s2^T @ s2
    {
        int p = t >> 4, q = t & 15;
        float a1 = 0.f, a2 = 0.f;
        for (int a = 0; a < 64; a++) {
            float sp = s2S[a*16 + p];
            a1 += sp * As2[a*16 + q];
            a2 += sp * s2S[a*16 + q];
        }
        pa2[t] = a1; sts2[t] = a2;
    }
    __syncthreads();

    float tr2 = k6_sum((t < 16) ? pa2[t*17] : 0.f, redb, scal);
    float dv = 0.f;
    if (t < 64) {
        float q2 = 0.f;
        for (int c = 0; c < 16; c++) { float u = s2S[t*16 + c]; q2 += u*u; }
        dv = deg2[t] * q2;
    }
    float den2 = k6_sum(dv, redb, scal) + 1e-10f;
    float mc2 = -tr2 / den2;

    float f2 = sts2[t] * sts2[t];
    float norm2 = sqrtf(k6_sum(f2, redb, scal));
    float u2 = sts2[t] / (norm2 + 1e-10f) - (((t >> 4) == (t & 15)) ? 0.25f : 0.f);
    float o2 = sqrtf(k6_sum(u2*u2, redb, scal));

    if (t == 0) { out[0] = mc1; out[1] = o1; out[2] = mc2; out[3] = o2; }
}

// ---------------- launch ----------------
extern "C" void kernel_launch(void* const* d_in, const int* in_sizes, int n_in,
                              void* d_out, int out_size) {
    const float* x      = (const float*)d_in[0];
    const int*   ei     = (const int*)  d_in[1];
    const float* dm     = (const float*)d_in[2];
    const float* W1rel  = (const float*)d_in[3];
    const float* b1     = (const float*)d_in[4];
    const float* W1root = (const float*)d_in[5];
    const float* pW1    = (const float*)d_in[6];
    const float* pb1    = (const float*)d_in[7];
    const float* g1     = (const float*)d_in[8];
    const float* be1    = (const float*)d_in[9];
    const float* W2rel  = (const float*)d_in[10];
    const float* b2     = (const float*)d_in[11];
    const float* W2root = (const float*)d_in[12];
    const float* pW2    = (const float*)d_in[13];
    const float* pb2    = (const float*)d_in[14];
    const float* g2     = (const float*)d_in[15];
    const float* be2    = (const float*)d_in[16];
    float* out = (float*)d_out;
    const int* row = ei;
    const int* col = ei + EE;

    cudaFuncSetAttribute(k3, cudaFuncAttributeMaxDynamicSharedMemorySize, K3_SMEM_BYTES);
    cudaFuncSetAttribute(k6, cudaFuncAttributeMaxDynamicSharedMemorySize, K6_SMEM_BYTES);

    kzero<<<512, 256>>>();
    kscatter1<<<4096, 256>>>(x, dm, row, col);
    k3<<<296, 128, K3_SMEM_BYTES>>>(x, dm, W1rel, b1, W1root, pW1, pb1, g1, be1, out + 4);
    kscatter2<<<4096, 256>>>(row, col);
    k5<<<296, 256>>>();
    k6<<<1, 256, K6_SMEM_BYTES>>>(W2rel, b2, W2root, pW2, pb2, g2, be2, out, out + 4 + (size_t)NN*C1N);
}

// round 2
// speedup vs baseline: 1.1687x; 1.1687x over previous
#include <cuda_runtime.h>
#include <math.h>

#define NN 50000
#define EE 800000
#define INC 64
#define HC 128
#define C1N 64
#define C2N 16
#define LN_EPS 1e-5f
#define THRESH1 (1.0f/63.0f)

typedef unsigned long long u64;

// ---------------- device scratch ----------------
__device__ __align__(16) float d_agg[NN*INC];
__device__ __align__(16) float d_x1[NN*HC];
__device__ __align__(16) float d_s[NN*C1N];
__device__ __align__(16) float d_As[NN*C1N];
__device__ __align__(16) float d_deg[NN];
__device__ __align__(16) float d_pooled[C1N*256];
__device__ float d_den;
__device__ __align__(16) float d_Wcat[HC*HC];   // [k][h] k-major cat(W1rel,W1root)^T
__device__ __align__(16) float d_pW1t[HC*C1N];  // [k][c] k-major pW1^T

__device__ __forceinline__ void red_add4(float* addr, float4 v) {
    asm volatile("red.global.add.v4.f32 [%0], {%1,%2,%3,%4};"
                 :: "l"(addr), "f"(v.x), "f"(v.y), "f"(v.z), "f"(v.w) : "memory");
}
__device__ __forceinline__ u64 dup2(float a) {
    u64 r; asm("mov.b64 %0, {%1, %1};" : "=l"(r) : "f"(a)); return r;
}
__device__ __forceinline__ void ffma2(u64& d, u64 a, u64 b) {
    asm("fma.rn.f32x2 %0, %1, %2, %0;" : "+l"(d) : "l"(a), "l"(b));
}
__device__ __forceinline__ float2 unpk(u64 v) {
    float2 r; asm("mov.b64 {%0, %1}, %2;" : "=f"(r.x), "=f"(r.y) : "l"(v)); return r;
}

// ---------------- zero scratch ----------------
__global__ void kzero() {
    int i0 = blockIdx.x*blockDim.x + threadIdx.x, st = gridDim.x*blockDim.x;
    for (int i = i0; i < NN*INC; i += st) { d_agg[i] = 0.f; d_As[i] = 0.f; }
    for (int i = i0; i < NN;     i += st) d_deg[i] = 0.f;
    for (int i = i0; i < C1N*256; i += st) d_pooled[i] = 0.f;
    if (i0 == 0) d_den = 0.f;
}

// ---------------- one-time weight transpose ----------------
__global__ void kprep(const float* __restrict__ W1rel, const float* __restrict__ W1root,
                      const float* __restrict__ pW1) {
    int i = blockIdx.x*blockDim.x + threadIdx.x;
    if (i < HC*HC) {
        int k = i >> 7, h = i & 127;
        d_Wcat[i] = (k < 64) ? W1rel[h*64 + k] : W1root[h*64 + (k - 64)];
    }
    if (i < HC*C1N) {
        int k = i >> 6, c = i & 63;
        d_pW1t[i] = pW1[c*128 + k];
    }
}

// ---------------- scatter 1: agg[col] += x[row]*dm[row]; deg[row] += 1 ----------------
__global__ void kscatter1(const float* __restrict__ x, const float* __restrict__ dm,
                          const int* __restrict__ row, const int* __restrict__ col) {
    int i0 = blockIdx.x*blockDim.x + threadIdx.x, st = gridDim.x*blockDim.x;
    for (int i = i0; i < EE*16; i += st) {
        int e = i >> 4, c = i & 15;
        int r = row[e];
        if (c == 0) atomicAdd(&d_deg[r], 1.0f);
        float m = dm[r];
        if (m != 0.0f) {
            int d = col[e];
            float4 v = ((const float4*)(x + (size_t)r*INC))[c];
            v.x *= m; v.y *= m; v.z *= m; v.w *= m;
            red_add4((float*)(((float4*)(d_agg + (size_t)d*INC)) + c), v);
        }
    }
}

// ---------------- scatter 2: A_s[row] += s[col] ----------------
__global__ void kscatter2(const int* __restrict__ row, const int* __restrict__ col) {
    int i0 = blockIdx.x*blockDim.x + threadIdx.x, st = gridDim.x*blockDim.x;
    for (int i = i0; i < EE*16; i += st) {
        int e = i >> 4, c = i & 15;
        int srcn = col[e];
        int dstn = row[e];
        float4 v = ((const float4*)(d_s + (size_t)srcn*C1N))[c];
        red_add4((float*)(((float4*)(d_As + (size_t)dstn*C1N)) + c), v);
    }
}

// ---------------- kA: X1 = relu([agg|x*dm] @ Wcat^T + b1), 64-node tiles ----------------
// smem: Bs[128][128] k-major weights (64KB) + As[128][68] k-major inputs + bias[128]
#define KA_SMEM_FLOATS (128*128 + 128*68 + 128)
#define KA_SMEM_BYTES  (KA_SMEM_FLOATS*4)

__global__ void __launch_bounds__(128) kA(const float* __restrict__ x,
                                          const float* __restrict__ dm,
                                          const float* __restrict__ b1) {
    extern __shared__ float sm[];
    float* Bs   = sm;               // 16384
    float* As   = Bs + 128*128;     // 8704 (stride 68)
    float* bias = As + 128*68;      // 128

    int t = threadIdx.x;
    for (int i = t; i < 128*128; i += 128) Bs[i] = d_Wcat[i];
    bias[t] = b1[t];

    int nb = blockIdx.x * 64;
    {
        int m = t & 63, half = t >> 6;
        int node = nb + m;
        bool valid = node < NN;
        float dmn = valid ? dm[node] : 0.f;
        for (int q = half; q < 32; q += 2) {
            float4 v;
            if (valid) {
                if (q < 16) v = ((const float4*)(d_agg + (size_t)node*INC))[q];
                else {
                    v = ((const float4*)(x + (size_t)node*INC))[q - 16];
                    v.x *= dmn; v.y *= dmn; v.z *= dmn; v.w *= dmn;
                }
            } else v = make_float4(0.f, 0.f, 0.f, 0.f);
            int k0 = q * 4;
            As[(k0+0)*68 + m] = v.x;
            As[(k0+1)*68 + m] = v.y;
            As[(k0+2)*68 + m] = v.z;
            As[(k0+3)*68 + m] = v.w;
        }
    }
    __syncthreads();

    int tx = t & 15, ty = t >> 4;
    u64 acc[8][4];
    #pragma unroll
    for (int i = 0; i < 8; i++) { acc[i][0]=0; acc[i][1]=0; acc[i][2]=0; acc[i][3]=0; }

    #pragma unroll 4
    for (int k = 0; k < 128; k++) {
        const float* ap = As + k*68 + ty*8;
        float4 aA = *(const float4*)ap;
        float4 aB = *(const float4*)(ap + 4);
        const u64* bp0 = (const u64*)(Bs + k*128 + tx*4);
        const u64* bp1 = (const u64*)(Bs + k*128 + 64 + tx*4);
        u64 B0 = bp0[0], B1 = bp0[1], B2 = bp1[0], B3 = bp1[1];
        float av[8] = {aA.x, aA.y, aA.z, aA.w, aB.x, aB.y, aB.z, aB.w};
        #pragma unroll
        for (int i = 0; i < 8; i++) {
            u64 Ai = dup2(av[i]);
            ffma2(acc[i][0], Ai, B0);
            ffma2(acc[i][1], Ai, B1);
            ffma2(acc[i][2], Ai, B2);
            ffma2(acc[i][3], Ai, B3);
        }
    }

    float b0 = bias[tx*4+0], b1v = bias[tx*4+1], b2v = bias[tx*4+2], b3v = bias[tx*4+3];
    float c0 = bias[64+tx*4+0], c1 = bias[64+tx*4+1], c2 = bias[64+tx*4+2], c3 = bias[64+tx*4+3];
    #pragma unroll
    for (int i = 0; i < 8; i++) {
        int nd = nb + ty*8 + i;
        if (nd < NN) {
            float2 p0 = unpk(acc[i][0]), p1 = unpk(acc[i][1]);
            float2 p2 = unpk(acc[i][2]), p3 = unpk(acc[i][3]);
            float4 o0 = make_float4(fmaxf(p0.x+b0,0.f), fmaxf(p0.y+b1v,0.f),
                                    fmaxf(p1.x+b2v,0.f), fmaxf(p1.y+b3v,0.f));
            float4 o1 = make_float4(fmaxf(p2.x+c0,0.f), fmaxf(p2.y+c1,0.f),
                                    fmaxf(p3.x+c2,0.f), fmaxf(p3.y+c3,0.f));
            *((float4*)(d_x1 + (size_t)nd*HC + tx*4))      = o0;
            *((float4*)(d_x1 + (size_t)nd*HC + 64 + tx*4)) = o1;
        }
    }
}

// ---------------- kB: s1raw = X1 @ pW1^T + pb1, then LN + log_softmax fused ----------------
#define KB_SMEM_FLOATS (128*64 + 128*68 + 64*68 + 64*3)
#define KB_SMEM_BYTES  (KB_SMEM_FLOATS*4)

__global__ void __launch_bounds__(128) kB(const float* __restrict__ pb1,
                                          const float* __restrict__ g1,
                                          const float* __restrict__ be1,
                                          float* __restrict__ ls1out) {
    extern __shared__ float sm[];
    float* Bs   = sm;              // 8192  pW1t [k][c]
    float* As   = Bs + 128*64;     // 8704  x1 tile [k][m] stride 68
    float* s1S  = As + 128*68;     // 4352  [m][c] stride 68
    float* pb1s = s1S + 64*68;
    float* g1s  = pb1s + 64;
    float* be1s = g1s + 64;

    int t = threadIdx.x;
    for (int i = t; i < 128*64; i += 128) Bs[i] = d_pW1t[i];
    if (t < 64) { pb1s[t] = pb1[t]; g1s[t] = g1[t]; be1s[t] = be1[t]; }

    int nb = blockIdx.x * 64;
    {
        int m = t & 63, half = t >> 6;
        int node = nb + m;
        bool valid = node < NN;
        for (int q = half; q < 32; q += 2) {
            float4 v = valid ? ((const float4*)(d_x1 + (size_t)node*HC))[q]
                             : make_float4(0.f,0.f,0.f,0.f);
            int k0 = q * 4;
            As[(k0+0)*68 + m] = v.x;
            As[(k0+1)*68 + m] = v.y;
            As[(k0+2)*68 + m] = v.z;
            As[(k0+3)*68 + m] = v.w;
        }
    }
    __syncthreads();

    int tx = t & 15, ty = t >> 4;
    u64 acc[8][2];
    #pragma unroll
    for (int i = 0; i < 8; i++) { acc[i][0]=0; acc[i][1]=0; }

    #pragma unroll 4
    for (int k = 0; k < 128; k++) {
        const float* ap = As + k*68 + ty*8;
        float4 aA = *(const float4*)ap;
        float4 aB = *(const float4*)(ap + 4);
        const u64* bp = (const u64*)(Bs + k*64 + tx*4);
        u64 B0 = bp[0], B1 = bp[1];
        float av[8] = {aA.x, aA.y, aA.z, aA.w, aB.x, aB.y, aB.z, aB.w};
        #pragma unroll
        for (int i = 0; i < 8; i++) {
            u64 Ai = dup2(av[i]);
            ffma2(acc[i][0], Ai, B0);
            ffma2(acc[i][1], Ai, B1);
        }
    }

    float q0 = pb1s[tx*4+0], q1 = pb1s[tx*4+1], q2 = pb1s[tx*4+2], q3 = pb1s[tx*4+3];
    #pragma unroll
    for (int i = 0; i < 8; i++) {
        float2 p0 = unpk(acc[i][0]), p1 = unpk(acc[i][1]);
        float* rowp = s1S + (ty*8 + i)*68 + tx*4;
        rowp[0] = p0.x + q0;
        rowp[1] = p0.y + q1;
        rowp[2] = p1.x + q2;
        rowp[3] = p1.y + q3;
    }
    __syncthreads();

    if (t < 64) {
        int node = nb + t;
        if (node < NN) {
            float v[64];
            #pragma unroll
            for (int c4 = 0; c4 < 16; c4++)
                ((float4*)v)[c4] = ((const float4*)(s1S + t*68))[c4];
            float mu = 0.f, msq = 0.f;
            #pragma unroll
            for (int c = 0; c < 64; c++) { mu += v[c]; msq += v[c]*v[c]; }
            mu *= (1.f/64.f); msq *= (1.f/64.f);
            float rstd = rsqrtf(msq - mu*mu + LN_EPS);
            float mx = -1e30f;
            #pragma unroll
            for (int c = 0; c < 64; c++) {
                v[c] = (v[c] - mu) * rstd * g1s[c] + be1s[c];
                mx = fmaxf(mx, v[c]);
            }
            float es = 0.f;
            #pragma unroll
            for (int c = 0; c < 64; c++) es += __expf(v[c] - mx);
            float lse = mx + __logf(es);
            float* lsp = ls1out + (size_t)node*C1N;
            float* sp  = d_s + (size_t)node*C1N;
            #pragma unroll
            for (int c4 = 0; c4 < 16; c4++) {
                float l0 = v[c4*4+0]-lse, l1 = v[c4*4+1]-lse, l2 = v[c4*4+2]-lse, l3 = v[c4*4+3]-lse;
                ((float4*)lsp)[c4] = make_float4(l0, l1, l2, l3);
                ((float4*)sp)[c4]  = make_float4(__expf(l0), __expf(l1), __expf(l2), __expf(l3));
            }
        }
    }
}

// ---------------- k5: pooled[a][c] = sum_i s[i,a]*V[i,c]; den ----------------
__global__ void __launch_bounds__(256, 2) k5() {
    __shared__ float V8[8][256];
    __shared__ __align__(8) float S8[8][64];
    __shared__ float D8[8];
    __shared__ float redw[8];

    u64 acc[32];
    #pragma unroll
    for (int p = 0; p < 32; p++) acc[p] = 0;
    float denAcc = 0.f;

    int t = threadIdx.x;
    int per = (NN + gridDim.x - 1) / gridDim.x;
    int n0 = blockIdx.x * per;
    int n1 = n0 + per; if (n1 > NN) n1 = NN;

    for (int nb = n0; nb < n1; nb += 8) {
        int cnt = n1 - nb; if (cnt > 8) cnt = 8;
        for (int i = t; i < cnt*256; i += 256) {
            int ni = i >> 8, c = i & 255;
            size_t node = (size_t)(nb + ni);
            float val;
            if (c < 128)      val = d_x1[node*HC + c];
            else if (c < 192) val = d_As[node*C1N + (c - 128)];
            else              val = d_s[node*C1N + (c - 192)];
            V8[ni][c] = val;
        }
        for (int i = t; i < cnt*64; i += 256) {
            int ni = i >> 6, a = i & 63;
            S8[ni][a] = d_s[(size_t)(nb + ni)*C1N + a];
        }
        if (t < cnt) D8[t] = d_deg[nb + t];
        __syncthreads();

        for (int ni = 0; ni < cnt; ni++) {
            u64 vd = dup2(V8[ni][t]);
            const u64* sp = (const u64*)S8[ni];
            #pragma unroll
            for (int p = 0; p < 32; p++) ffma2(acc[p], sp[p], vd);
        }
        for (int i = t; i < cnt*64; i += 256) {
            int ni = i >> 6, a = i & 63;
            float sv = S8[ni][a];
            denAcc += D8[ni] * sv * sv;
        }
        __syncthreads();
    }

    #pragma unroll
    for (int p = 0; p < 32; p++) {
        float2 pr = unpk(acc[p]);
        atomicAdd(&d_pooled[(2*p+0)*256 + t], pr.x);
        atomicAdd(&d_pooled[(2*p+1)*256 + t], pr.y);
    }

    #pragma unroll
    for (int o = 16; o; o >>= 1) denAcc += __shfl_xor_sync(0xffffffffu, denAcc, o);
    if ((t & 31) == 0) redw[t >> 5] = denAcc;
    __syncthreads();
    if (t == 0) {
        float s = 0.f;
        for (int w = 0; w < 8; w++) s += redw[w];
        atomicAdd(&d_den, s);
    }
}

// ---------------- final tiny stage (single block) ----------------
__device__ __forceinline__ float k6_sum(float v, float* redb, float* scal) {
    redb[threadIdx.x] = v;
    __syncthreads();
    if (threadIdx.x == 0) {
        float s = 0.f;
        for (int i = 0; i < 256; i++) s += redb[i];
        scal[0] = s;
    }
    __syncthreads();
    float r = scal[0];
    __syncthreads();
    return r;
}

#define K6_SMEM_FLOATS (8192 + 4096 + 4096 + 4096 + 8192 + 8192 + 1024 + 1024 + 1024 + 256 + 256 + 64 + 64 + 256 + 8)
#define K6_SMEM_BYTES  (K6_SMEM_FLOATS*4)

__global__ void __launch_bounds__(256, 1) k6(
    const float* __restrict__ W2rel, const float* __restrict__ b2, const float* __restrict__ W2root,
    const float* __restrict__ pW2, const float* __restrict__ pb2,
    const float* __restrict__ g2, const float* __restrict__ be2,
    float* __restrict__ out, float* __restrict__ ls2out) {
    extern __shared__ float sm[];
    float* px    = sm;             // 8192
    float* paS   = px + 8192;      // 4096
    float* stsS  = paS + 4096;     // 4096
    float* Ms    = stsS + 4096;    // 4096
    float* t1S   = Ms + 4096;      // 8192
    float* x2S   = t1S + 8192;     // 8192
    float* s2raw = x2S + 8192;     // 1024
    float* s2S   = s2raw + 1024;   // 1024
    float* As2   = s2S + 1024;     // 1024
    float* pa2   = As2 + 1024;     // 256
    float* sts2  = pa2 + 256;      // 256
    float* dsi   = sts2 + 256;     // 64
    float* deg2  = dsi + 64;       // 64
    float* redb  = deg2 + 64;      // 256
    float* scal  = redb + 256;     // 8

    int t = threadIdx.x;
    for (int i = t; i < 8192; i += 256) px[i]   = d_pooled[((i >> 7) << 8) + (i & 127)];
    for (int i = t; i < 4096; i += 256) paS[i]  = d_pooled[((i >> 6) << 8) + 128 + (i & 63)];
    for (int i = t; i < 4096; i += 256) stsS[i] = d_pooled[((i >> 6) << 8) + 192 + (i & 63)];
    __syncthreads();

    float tr = k6_sum((t < 64) ? paS[t*64 + t] : 0.f, redb, scal);
    float mc1 = -tr / (d_den + 1e-10f);

    float fq = 0.f;
    for (int i = t; i < 4096; i += 256) { float u = stsS[i]; fq += u*u; }
    float norm = sqrtf(k6_sum(fq, redb, scal));
    float oq = 0.f;
    for (int i = t; i < 4096; i += 256) {
        float u = stsS[i] / (norm + 1e-10f) - (((i >> 6) == (i & 63)) ? 0.125f : 0.f);
        oq += u*u;
    }
    float o1 = sqrtf(k6_sum(oq, redb, scal));

    if (t < 64) {
        float rs = 0.f;
        for (int b = 0; b < 64; b++) if (b != t) rs += paS[t*64 + b];
        dsi[t] = 1.f / (sqrtf(rs) + 1e-15f);
    }
    __syncthreads();
    for (int i = t; i < 4096; i += 256) {
        int a = i >> 6, b = i & 63;
        float adjn = (a == b) ? 0.f : paS[i] * dsi[a] * dsi[b];
        Ms[i] = (adjn > THRESH1) ? 1.f : 0.f;
    }
    __syncthreads();

    for (int i = t; i < 8192; i += 256) {
        int a = i >> 7, f = i & 127;
        float acc = 0.f;
        for (int b = 0; b < 64; b++) acc += Ms[b*64 + a] * px[b*128 + f];
        t1S[i] = acc;
    }
    __syncthreads();

    for (int i = t; i < 8192; i += 256) {
        int a = i >> 7, h = i & 127;
        float acc = b2[h];
        const float* wr = W2rel + h*128;
        const float* wo = W2root + h*128;
        for (int f = 0; f < 128; f++) acc += t1S[a*128 + f] * wr[f] + px[a*128 + f] * wo[f];
        x2S[i] = fmaxf(acc, 0.f);
    }
    __syncthreads();

    for (int i = t; i < 1024; i += 256) {
        int a = i >> 4, c = i & 15;
        float acc = pb2[c];
        const float* w = pW2 + c*128;
        for (int h = 0; h < 128; h++) acc += x2S[a*128 + h] * w[h];
        s2raw[i] = acc;
    }
    __syncthreads();

    if (t < 64) {
        float mu = 0.f, msq = 0.f;
        for (int c = 0; c < 16; c++) { float u = s2raw[t*16 + c]; mu += u; msq += u*u; }
        mu *= (1.f/16.f); msq *= (1.f/16.f);
        float rstd = rsqrtf(msq - mu*mu + LN_EPS);
        float nv[16]; float mx = -1e30f;
        for (int c = 0; c < 16; c++) {
            nv[c] = (s2raw[t*16 + c] - mu) * rstd * g2[c] + be2[c];
            mx = fmaxf(mx, nv[c]);
        }
        float es = 0.f;
        for (int c = 0; c < 16; c++) es += expf(nv[c] - mx);
        float lse = mx + logf(es);
        for (int c = 0; c < 16; c++) {
            float ls = nv[c] - lse;
            ls2out[t*16 + c] = ls;
            s2S[t*16 + c] = expf(ls);
        }
        float dg = 0.f;
        for (int b = 0; b < 64; b++) dg += Ms[t*64 + b];
        deg2[t] = dg;
    }
    __syncthreads();

    for (int i = t; i < 1024; i += 256) {
        int a = i >> 4, c = i & 15;
        float acc = 0.f;
        for (int b = 0; b < 64; b++) acc += Ms[a*64 + b] * s2S[b*16 + c];
        As2[i] = acc;
    }
    __syncthreads();

    {
        int p = t >> 4, q = t & 15;
        float a1 = 0.f, a2 = 0.f;
        for (int a = 0; a < 64; a++) {
            float sp = s2S[a*16 + p];
            a1 += sp * As2[a*16 + q];
            a2 += sp * s2S[a*16 + q];
        }
        pa2[t] = a1; sts2[t] = a2;
    }
    __syncthreads();

    float tr2 = k6_sum((t < 16) ? pa2[t*17] : 0.f, redb, scal);
    float dv = 0.f;
    if (t < 64) {
        float q2 = 0.f;
        for (int c = 0; c < 16; c++) { float u = s2S[t*16 + c]; q2 += u*u; }
        dv = deg2[t] * q2;
    }
    float den2 = k6_sum(dv, redb, scal) + 1e-10f;
    float mc2 = -tr2 / den2;

    float f2 = sts2[t] * sts2[t];
    float norm2 = sqrtf(k6_sum(f2, redb, scal));
    float u2 = sts2[t] / (norm2 + 1e-10f) - (((t >> 4) == (t & 15)) ? 0.25f : 0.f);
    float o2 = sqrtf(k6_sum(u2*u2, redb, scal));

    if (t == 0) { out[0] = mc1; out[1] = o1; out[2] = mc2; out[3] = o2; }
}

// ---------------- launch ----------------
extern "C" void kernel_launch(void* const* d_in, const int* in_sizes, int n_in,
                              void* d_out, int out_size) {
    const float* x      = (const float*)d_in[0];
    const int*   ei     = (const int*)  d_in[1];
    const float* dm     = (const float*)d_in[2];
    const float* W1rel  = (const float*)d_in[3];
    const float* b1     = (const float*)d_in[4];
    const float* W1root = (const float*)d_in[5];
    const float* pW1    = (const float*)d_in[6];
    const float* pb1    = (const float*)d_in[7];
    const float* g1     = (const float*)d_in[8];
    const float* be1    = (const float*)d_in[9];
    const float* W2rel  = (const float*)d_in[10];
    const float* b2     = (const float*)d_in[11];
    const float* W2root = (const float*)d_in[12];
    const float* pW2    = (const float*)d_in[13];
    const float* pb2    = (const float*)d_in[14];
    const float* g2     = (const float*)d_in[15];
    const float* be2    = (const float*)d_in[16];
    float* out = (float*)d_out;
    const int* row = ei;
    const int* col = ei + EE;

    cudaFuncSetAttribute(kA, cudaFuncAttributeMaxDynamicSharedMemorySize, KA_SMEM_BYTES);
    cudaFuncSetAttribute(kB, cudaFuncAttributeMaxDynamicSharedMemorySize, KB_SMEM_BYTES);
    cudaFuncSetAttribute(k6, cudaFuncAttributeMaxDynamicSharedMemorySize, K6_SMEM_BYTES);

    int nblk = (NN + 63) / 64;  // 782

    kzero<<<512, 256>>>();
    kprep<<<64, 256>>>(W1rel, W1root, pW1);
    kscatter1<<<4096, 256>>>(x, dm, row, col);
    kA<<<nblk, 128, KA_SMEM_BYTES>>>(x, dm, b1);
    kB<<<nblk, 128, KB_SMEM_BYTES>>>(pb1, g1, be1, out + 4);
    kscatter2<<<4096, 256>>>(row, col);
    k5<<<296, 256>>>();
    k6<<<1, 256, K6_SMEM_BYTES>>>(W2rel, b2, W2root, pW2, pb2, g2, be2, out, out + 4 + (size_t)NN*C1N);
}

// round 3
// speedup vs baseline: 4.2263x; 3.6162x over previous
#include <cuda_runtime.h>
#include <math.h>

#define NN 50000
#define EE 800000
#define INC 64
#define HC 128
#define C1N 64
#define C2N 16
#define LN_EPS 1e-5f
#define THRESH1 (1.0f/63.0f)

typedef unsigned long long u64;

// ---------------- device scratch ----------------
__device__ __align__(16) float d_agg[NN*INC];
__device__ __align__(16) float d_x1[NN*HC];
__device__ __align__(16) float d_s[NN*C1N];
__device__ __align__(16) float d_As[NN*C1N];
__device__ __align__(16) float d_deg[NN];
__device__ __align__(16) float d_pooled[C1N*256];
__device__ float d_den;
__device__ __align__(16) float d_Wcat[HC*HC];   // [k][h]
__device__ __align__(16) float d_pW1t[HC*C1N];  // [k][c]

__device__ __forceinline__ void red_add4(float* addr, float4 v) {
    asm volatile("red.global.add.v4.f32 [%0], {%1,%2,%3,%4};"
                 :: "l"(addr), "f"(v.x), "f"(v.y), "f"(v.z), "f"(v.w) : "memory");
}
__device__ __forceinline__ u64 dup2(float a) {
    u64 r; asm("mov.b64 %0, {%1, %1};" : "=l"(r) : "f"(a)); return r;
}
__device__ __forceinline__ void ffma2(u64& d, u64 a, u64 b) {
    asm("fma.rn.f32x2 %0, %1, %2, %0;" : "+l"(d) : "l"(a), "l"(b));
}
__device__ __forceinline__ float2 unpk(u64 v) {
    float2 r; asm("mov.b64 {%0, %1}, %2;" : "=f"(r.x), "=f"(r.y) : "l"(v)); return r;
}

// ---------------- zero scratch ----------------
__global__ void kzero() {
    int i0 = blockIdx.x*blockDim.x + threadIdx.x, st = gridDim.x*blockDim.x;
    for (int i = i0; i < NN*INC; i += st) { d_agg[i] = 0.f; d_As[i] = 0.f; }
    for (int i = i0; i < NN;     i += st) d_deg[i] = 0.f;
    for (int i = i0; i < C1N*256; i += st) d_pooled[i] = 0.f;
    if (i0 == 0) d_den = 0.f;
}

// ---------------- one-time weight transpose ----------------
__global__ void kprep(const float* __restrict__ W1rel, const float* __restrict__ W1root,
                      const float* __restrict__ pW1) {
    int i = blockIdx.x*blockDim.x + threadIdx.x;
    if (i < HC*HC) {
        int k = i >> 7, h = i & 127;
        d_Wcat[i] = (k < 64) ? W1rel[h*64 + k] : W1root[h*64 + (k - 64)];
    }
    if (i < HC*C1N) {
        int k = i >> 6, c = i & 63;
        d_pW1t[i] = pW1[c*128 + k];
    }
}

// ---------------- scatter 1 ----------------
__global__ void kscatter1(const float* __restrict__ x, const float* __restrict__ dm,
                          const int* __restrict__ row, const int* __restrict__ col) {
    int i0 = blockIdx.x*blockDim.x + threadIdx.x, st = gridDim.x*blockDim.x;
    for (int i = i0; i < EE*16; i += st) {
        int e = i >> 4, c = i & 15;
        int r = row[e];
        if (c == 0) atomicAdd(&d_deg[r], 1.0f);
        float m = dm[r];
        if (m != 0.0f) {
            int d = col[e];
            float4 v = ((const float4*)(x + (size_t)r*INC))[c];
            v.x *= m; v.y *= m; v.z *= m; v.w *= m;
            red_add4((float*)(((float4*)(d_agg + (size_t)d*INC)) + c), v);
        }
    }
}

// ---------------- scatter 2 ----------------
__global__ void kscatter2(const int* __restrict__ row, const int* __restrict__ col) {
    int i0 = blockIdx.x*blockDim.x + threadIdx.x, st = gridDim.x*blockDim.x;
    for (int i = i0; i < EE*16; i += st) {
        int e = i >> 4, c = i & 15;
        int srcn = col[e];
        int dstn = row[e];
        float4 v = ((const float4*)(d_s + (size_t)srcn*C1N))[c];
        red_add4((float*)(((float4*)(d_As + (size_t)dstn*C1N)) + c), v);
    }
}

// ---------------- kA ----------------
#define KA_SMEM_FLOATS (128*128 + 128*68 + 128)
#define KA_SMEM_BYTES  (KA_SMEM_FLOATS*4)

__global__ void __launch_bounds__(128) kA(const float* __restrict__ x,
                                          const float* __restrict__ dm,
                                          const float* __restrict__ b1) {
    extern __shared__ float sm[];
    float* Bs   = sm;
    float* As   = Bs + 128*128;
    float* bias = As + 128*68;

    int t = threadIdx.x;
    for (int i = t; i < 128*128; i += 128) Bs[i] = d_Wcat[i];
    bias[t] = b1[t];

    int nb = blockIdx.x * 64;
    {
        int m = t & 63, half = t >> 6;
        int node = nb + m;
        bool valid = node < NN;
        float dmn = valid ? dm[node] : 0.f;
        for (int q = half; q < 32; q += 2) {
            float4 v;
            if (valid) {
                if (q < 16) v = ((const float4*)(d_agg + (size_t)node*INC))[q];
                else {
                    v = ((const float4*)(x + (size_t)node*INC))[q - 16];
                    v.x *= dmn; v.y *= dmn; v.z *= dmn; v.w *= dmn;
                }
            } else v = make_float4(0.f, 0.f, 0.f, 0.f);
            int k0 = q * 4;
            As[(k0+0)*68 + m] = v.x;
            As[(k0+1)*68 + m] = v.y;
            As[(k0+2)*68 + m] = v.z;
            As[(k0+3)*68 + m] = v.w;
        }
    }
    __syncthreads();

    int tx = t & 15, ty = t >> 4;
    u64 acc[8][4];
    #pragma unroll
    for (int i = 0; i < 8; i++) { acc[i][0]=0; acc[i][1]=0; acc[i][2]=0; acc[i][3]=0; }

    #pragma unroll 4
    for (int k = 0; k < 128; k++) {
        const float* ap = As + k*68 + ty*8;
        float4 aA = *(const float4*)ap;
        float4 aB = *(const float4*)(ap + 4);
        const u64* bp0 = (const u64*)(Bs + k*128 + tx*4);
        const u64* bp1 = (const u64*)(Bs + k*128 + 64 + tx*4);
        u64 B0 = bp0[0], B1 = bp0[1], B2 = bp1[0], B3 = bp1[1];
        float av[8] = {aA.x, aA.y, aA.z, aA.w, aB.x, aB.y, aB.z, aB.w};
        #pragma unroll
        for (int i = 0; i < 8; i++) {
            u64 Ai = dup2(av[i]);
            ffma2(acc[i][0], Ai, B0);
            ffma2(acc[i][1], Ai, B1);
            ffma2(acc[i][2], Ai, B2);
            ffma2(acc[i][3], Ai, B3);
        }
    }

    float b0 = bias[tx*4+0], b1v = bias[tx*4+1], b2v = bias[tx*4+2], b3v = bias[tx*4+3];
    float c0 = bias[64+tx*4+0], c1 = bias[64+tx*4+1], c2 = bias[64+tx*4+2], c3 = bias[64+tx*4+3];
    #pragma unroll
    for (int i = 0; i < 8; i++) {
        int nd = nb + ty*8 + i;
        if (nd < NN) {
            float2 p0 = unpk(acc[i][0]), p1 = unpk(acc[i][1]);
            float2 p2 = unpk(acc[i][2]), p3 = unpk(acc[i][3]);
            float4 o0 = make_float4(fmaxf(p0.x+b0,0.f), fmaxf(p0.y+b1v,0.f),
                                    fmaxf(p1.x+b2v,0.f), fmaxf(p1.y+b3v,0.f));
            float4 o1 = make_float4(fmaxf(p2.x+c0,0.f), fmaxf(p2.y+c1,0.f),
                                    fmaxf(p3.x+c2,0.f), fmaxf(p3.y+c3,0.f));
            *((float4*)(d_x1 + (size_t)nd*HC + tx*4))      = o0;
            *((float4*)(d_x1 + (size_t)nd*HC + 64 + tx*4)) = o1;
        }
    }
}

// ---------------- kB ----------------
#define KB_SMEM_FLOATS (128*64 + 128*68 + 64*68 + 64*3)
#define KB_SMEM_BYTES  (KB_SMEM_FLOATS*4)

__global__ void __launch_bounds__(128) kB(const float* __restrict__ pb1,
                                          const float* __restrict__ g1,
                                          const float* __restrict__ be1,
                                          float* __restrict__ ls1out) {
    extern __shared__ float sm[];
    float* Bs   = sm;
    float* As   = Bs + 128*64;
    float* s1S  = As + 128*68;
    float* pb1s = s1S + 64*68;
    float* g1s  = pb1s + 64;
    float* be1s = g1s + 64;

    int t = threadIdx.x;
    for (int i = t; i < 128*64; i += 128) Bs[i] = d_pW1t[i];
    if (t < 64) { pb1s[t] = pb1[t]; g1s[t] = g1[t]; be1s[t] = be1[t]; }

    int nb = blockIdx.x * 64;
    {
        int m = t & 63, half = t >> 6;
        int node = nb + m;
        bool valid = node < NN;
        for (int q = half; q < 32; q += 2) {
            float4 v = valid ? ((const float4*)(d_x1 + (size_t)node*HC))[q]
                             : make_float4(0.f,0.f,0.f,0.f);
            int k0 = q * 4;
            As[(k0+0)*68 + m] = v.x;
            As[(k0+1)*68 + m] = v.y;
            As[(k0+2)*68 + m] = v.z;
            As[(k0+3)*68 + m] = v.w;
        }
    }
    __syncthreads();

    int tx = t & 15, ty = t >> 4;
    u64 acc[8][2];
    #pragma unroll
    for (int i = 0; i < 8; i++) { acc[i][0]=0; acc[i][1]=0; }

    #pragma unroll 4
    for (int k = 0; k < 128; k++) {
        const float* ap = As + k*68 + ty*8;
        float4 aA = *(const float4*)ap;
        float4 aB = *(const float4*)(ap + 4);
        const u64* bp = (const u64*)(Bs + k*64 + tx*4);
        u64 B0 = bp[0], B1 = bp[1];
        float av[8] = {aA.x, aA.y, aA.z, aA.w, aB.x, aB.y, aB.z, aB.w};
        #pragma unroll
        for (int i = 0; i < 8; i++) {
            u64 Ai = dup2(av[i]);
            ffma2(acc[i][0], Ai, B0);
            ffma2(acc[i][1], Ai, B1);
        }
    }

    float q0 = pb1s[tx*4+0], q1 = pb1s[tx*4+1], q2 = pb1s[tx*4+2], q3 = pb1s[tx*4+3];
    #pragma unroll
    for (int i = 0; i < 8; i++) {
        float2 p0 = unpk(acc[i][0]), p1 = unpk(acc[i][1]);
        float* rowp = s1S + (ty*8 + i)*68 + tx*4;
        rowp[0] = p0.x + q0;
        rowp[1] = p0.y + q1;
        rowp[2] = p1.x + q2;
        rowp[3] = p1.y + q3;
    }
    __syncthreads();

    if (t < 64) {
        int node = nb + t;
        if (node < NN) {
            float v[64];
            #pragma unroll
            for (int c4 = 0; c4 < 16; c4++)
                ((float4*)v)[c4] = ((const float4*)(s1S + t*68))[c4];
            float mu = 0.f, msq = 0.f;
            #pragma unroll
            for (int c = 0; c < 64; c++) { mu += v[c]; msq += v[c]*v[c]; }
            mu *= (1.f/64.f); msq *= (1.f/64.f);
            float rstd = rsqrtf(msq - mu*mu + LN_EPS);
            float mx = -1e30f;
            #pragma unroll
            for (int c = 0; c < 64; c++) {
                v[c] = (v[c] - mu) * rstd * g1s[c] + be1s[c];
                mx = fmaxf(mx, v[c]);
            }
            float es = 0.f;
            #pragma unroll
            for (int c = 0; c < 64; c++) es += __expf(v[c] - mx);
            float lse = mx + __logf(es);
            float* lsp = ls1out + (size_t)node*C1N;
            float* sp  = d_s + (size_t)node*C1N;
            #pragma unroll
            for (int c4 = 0; c4 < 16; c4++) {
                float l0 = v[c4*4+0]-lse, l1 = v[c4*4+1]-lse, l2 = v[c4*4+2]-lse, l3 = v[c4*4+3]-lse;
                ((float4*)lsp)[c4] = make_float4(l0, l1, l2, l3);
                ((float4*)sp)[c4]  = make_float4(__expf(l0), __expf(l1), __expf(l2), __expf(l3));
            }
        }
    }
}

// ---------------- k5 ----------------
__global__ void __launch_bounds__(256, 2) k5() {
    __shared__ float V8[8][256];
    __shared__ __align__(8) float S8[8][64];
    __shared__ float D8[8];
    __shared__ float redw[8];

    u64 acc[32];
    #pragma unroll
    for (int p = 0; p < 32; p++) acc[p] = 0;
    float denAcc = 0.f;

    int t = threadIdx.x;
    int per = (NN + gridDim.x - 1) / gridDim.x;
    int n0 = blockIdx.x * per;
    int n1 = n0 + per; if (n1 > NN) n1 = NN;

    for (int nb = n0; nb < n1; nb += 8) {
        int cnt = n1 - nb; if (cnt > 8) cnt = 8;
        for (int i = t; i < cnt*256; i += 256) {
            int ni = i >> 8, c = i & 255;
            size_t node = (size_t)(nb + ni);
            float val;
            if (c < 128)      val = d_x1[node*HC + c];
            else if (c < 192) val = d_As[node*C1N + (c - 128)];
            else              val = d_s[node*C1N + (c - 192)];
            V8[ni][c] = val;
        }
        for (int i = t; i < cnt*64; i += 256) {
            int ni = i >> 6, a = i & 63;
            S8[ni][a] = d_s[(size_t)(nb + ni)*C1N + a];
        }
        if (t < cnt) D8[t] = d_deg[nb + t];
        __syncthreads();

        for (int ni = 0; ni < cnt; ni++) {
            u64 vd = dup2(V8[ni][t]);
            const u64* sp = (const u64*)S8[ni];
            #pragma unroll
            for (int p = 0; p < 32; p++) ffma2(acc[p], sp[p], vd);
        }
        for (int i = t; i < cnt*64; i += 256) {
            int ni = i >> 6, a = i & 63;
            float sv = S8[ni][a];
            denAcc += D8[ni] * sv * sv;
        }
        __syncthreads();
    }

    #pragma unroll
    for (int p = 0; p < 32; p++) {
        float2 pr = unpk(acc[p]);
        atomicAdd(&d_pooled[(2*p+0)*256 + t], pr.x);
        atomicAdd(&d_pooled[(2*p+1)*256 + t], pr.y);
    }

    #pragma unroll
    for (int o = 16; o; o >>= 1) denAcc += __shfl_xor_sync(0xffffffffu, denAcc, o);
    if ((t & 31) == 0) redw[t >> 5] = denAcc;
    __syncthreads();
    if (t == 0) {
        float s = 0.f;
        for (int w = 0; w < 8; w++) s += redw[w];
        atomicAdd(&d_den, s);
    }
}

// ---------------- k6: final stage, all heavy reads staged in SMEM ----------------
__device__ __forceinline__ float k6_sum(float v, float* redw, float* scal) {
    #pragma unroll
    for (int o = 16; o; o >>= 1) v += __shfl_xor_sync(0xffffffffu, v, o);
    if ((threadIdx.x & 31) == 0) redw[threadIdx.x >> 5] = v;
    __syncthreads();
    if (threadIdx.x == 0) {
        float s = 0.f;
        for (int w = 0; w < 8; w++) s += redw[w];
        scal[0] = s;
    }
    __syncthreads();
    float r = scal[0];
    __syncthreads();
    return r;
}

// smem offsets (floats)
#define O_PX    0           // [64][132]
#define O_MS    8448        // [64][64]
#define O_T1    12544       // [64][132]
#define O_X2    20992       // [64][128]
#define O_WS    29184       // [128][130] weight staging; paS=WS+0, stsS=WS+4096
#define O_PW2   45824       // [128][16]
#define O_S2R   47872       // [64][16]
#define O_S2    48896
#define O_AS2   49920
#define O_PA2   50944
#define O_STS2  51200
#define O_DSI   51456
#define O_DEG2  51520
#define O_REDW  51584
#define O_SCAL  51648
#define K6_SMEM_FLOATS 51656
#define K6_SMEM_BYTES (K6_SMEM_FLOATS*4)

__global__ void __launch_bounds__(256, 1) k6(
    const float* __restrict__ W2rel, const float* __restrict__ b2, const float* __restrict__ W2root,
    const float* __restrict__ pW2, const float* __restrict__ pb2,
    const float* __restrict__ g2, const float* __restrict__ be2,
    float* __restrict__ out, float* __restrict__ ls2out) {
    extern __shared__ float sm[];
    float* px    = sm + O_PX;     // stride 132
    float* Ms    = sm + O_MS;
    float* t1S   = sm + O_T1;     // stride 132
    float* x2S   = sm + O_X2;     // stride 128
    float* WS    = sm + O_WS;     // stride 130 (transposed weights)
    float* paS   = WS;            // reuse (dead before WS staged)
    float* stsS  = WS + 4096;
    float* pW2S  = sm + O_PW2;
    float* s2raw = sm + O_S2R;
    float* s2S   = sm + O_S2;
    float* As2   = sm + O_AS2;
    float* pa2   = sm + O_PA2;
    float* sts2  = sm + O_STS2;
    float* dsi   = sm + O_DSI;
    float* deg2  = sm + O_DEG2;
    float* redw  = sm + O_REDW;
    float* scal  = sm + O_SCAL;

    int t = threadIdx.x;
    for (int i = t; i < 8192; i += 256) px[(i >> 7)*132 + (i & 127)] = d_pooled[((i >> 7) << 8) + (i & 127)];
    for (int i = t; i < 4096; i += 256) paS[i]  = d_pooled[((i >> 6) << 8) + 128 + (i & 63)];
    for (int i = t; i < 4096; i += 256) stsS[i] = d_pooled[((i >> 6) << 8) + 192 + (i & 63)];
    __syncthreads();

    // mc1
    float tr = k6_sum((t < 64) ? paS[t*64 + t] : 0.f, redw, scal);
    float mc1 = -tr / (d_den + 1e-10f);

    // ortho1
    float fq = 0.f;
    for (int i = t; i < 4096; i += 256) { float u = stsS[i]; fq += u*u; }
    float norm = sqrtf(k6_sum(fq, redw, scal));
    float oq = 0.f;
    for (int i = t; i < 4096; i += 256) {
        float u = stsS[i] / (norm + 1e-10f) - (((i >> 6) == (i & 63)) ? 0.125f : 0.f);
        oq += u*u;
    }
    float o1 = sqrtf(k6_sum(oq, redw, scal));

    // adj_norm -> M
    if (t < 64) {
        float rs = 0.f;
        for (int b = 0; b < 64; b++) if (b != t) rs += paS[t*64 + b];
        dsi[t] = 1.f / (sqrtf(rs) + 1e-15f);
    }
    __syncthreads();
    for (int i = t; i < 4096; i += 256) {
        int a = i >> 6, b = i & 63;
        float adjn = (a == b) ? 0.f : paS[i] * dsi[a] * dsi[b];
        Ms[i] = (adjn > THRESH1) ? 1.f : 0.f;
    }
    __syncthreads();

    // t1 = M^T @ px  (float4 over f)
    for (int i = t; i < 2048; i += 256) {
        int a = i >> 5, f4 = i & 31;
        float4 acc = make_float4(0.f, 0.f, 0.f, 0.f);
        for (int b = 0; b < 64; b++) {
            float ms = Ms[b*64 + a];
            float4 pv = ((const float4*)(px + b*132))[f4];
            acc.x += ms*pv.x; acc.y += ms*pv.y; acc.z += ms*pv.z; acc.w += ms*pv.w;
        }
        ((float4*)(t1S + a*132))[f4] = acc;
    }
    __syncthreads();

    // x2 = relu(t1 @ W2rel^T + px @ W2root^T + b2)  -- two staged passes
    int tx = t & 15, ty = t >> 4;   // tx: h-tile (8 cols), ty: a-tile (4 rows)
    u64 acc2[4][4];
    #pragma unroll
    for (int j = 0; j < 4; j++) { acc2[j][0]=0; acc2[j][1]=0; acc2[j][2]=0; acc2[j][3]=0; }

    // pass 1: W2rel with A = t1S
    for (int i = t; i < 16384; i += 256) WS[(i & 127)*130 + (i >> 7)] = W2rel[i];
    __syncthreads();
    for (int f = 0; f < 128; f++) {
        const u64* wp = (const u64*)(WS + f*130 + tx*8);
        u64 w0 = wp[0], w1 = wp[1], w2 = wp[2], w3 = wp[3];
        #pragma unroll
        for (int j = 0; j < 4; j++) {
            u64 Aj = dup2(t1S[(ty*4 + j)*132 + f]);
            ffma2(acc2[j][0], Aj, w0); ffma2(acc2[j][1], Aj, w1);
            ffma2(acc2[j][2], Aj, w2); ffma2(acc2[j][3], Aj, w3);
        }
    }
    __syncthreads();
    // pass 2: W2root with A = px
    for (int i = t; i < 16384; i += 256) WS[(i & 127)*130 + (i >> 7)] = W2root[i];
    __syncthreads();
    for (int f = 0; f < 128; f++) {
        const u64* wp = (const u64*)(WS + f*130 + tx*8);
        u64 w0 = wp[0], w1 = wp[1], w2 = wp[2], w3 = wp[3];
        #pragma unroll
        for (int j = 0; j < 4; j++) {
            u64 Aj = dup2(px[(ty*4 + j)*132 + f]);
            ffma2(acc2[j][0], Aj, w0); ffma2(acc2[j][1], Aj, w1);
            ffma2(acc2[j][2], Aj, w2); ffma2(acc2[j][3], Aj, w3);
        }
    }
    {
        float bb[8];
        #pragma unroll
        for (int p = 0; p < 8; p++) bb[p] = b2[tx*8 + p];
        #pragma unroll
        for (int j = 0; j < 4; j++) {
            int a = ty*4 + j;
            float2 p0 = unpk(acc2[j][0]), p1 = unpk(acc2[j][1]);
            float2 p2 = unpk(acc2[j][2]), p3 = unpk(acc2[j][3]);
            float4 o0 = make_float4(fmaxf(p0.x+bb[0],0.f), fmaxf(p0.y+bb[1],0.f),
                                    fmaxf(p1.x+bb[2],0.f), fmaxf(p1.y+bb[3],0.f));
            float4 o1 = make_float4(fmaxf(p2.x+bb[4],0.f), fmaxf(p2.y+bb[5],0.f),
                                    fmaxf(p3.x+bb[6],0.f), fmaxf(p3.y+bb[7],0.f));
            ((float4*)(x2S + a*128 + tx*8))[0] = o0;
            ((float4*)(x2S + a*128 + tx*8))[1] = o1;
        }
    }
    // stage pW2 transposed [h][c]
    for (int i = t; i < 2048; i += 256) pW2S[(i & 127)*16 + (i >> 7)] = pW2[i];
    __syncthreads();

    // s2raw = x2 @ pW2^T + pb2
    for (int i = t; i < 1024; i += 256) {
        int a = i >> 4, c = i & 15;
        float acc = pb2[c];
        for (int h = 0; h < 128; h++) acc += x2S[a*128 + h] * pW2S[h*16 + c];
        s2raw[i] = acc;
    }
    __syncthreads();

    // LN + log_softmax per row, deg2
    if (t < 64) {
        float mu = 0.f, msq = 0.f;
        for (int c = 0; c < 16; c++) { float u = s2raw[t*16 + c]; mu += u; msq += u*u; }
        mu *= (1.f/16.f); msq *= (1.f/16.f);
        float rstd = rsqrtf(msq - mu*mu + LN_EPS);
        float nv[16]; float mx = -1e30f;
        for (int c = 0; c < 16; c++) {
            nv[c] = (s2raw[t*16 + c] - mu) * rstd * g2[c] + be2[c];
            mx = fmaxf(mx, nv[c]);
        }
        float es = 0.f;
        for (int c = 0; c < 16; c++) es += expf(nv[c] - mx);
        float lse = mx + logf(es);
        for (int c = 0; c < 16; c++) {
            float ls = nv[c] - lse;
            ls2out[t*16 + c] = ls;
            s2S[t*16 + c] = expf(ls);
        }
        float dg = 0.f;
        for (int b = 0; b < 64; b++) dg += Ms[t*64 + b];
        deg2[t] = dg;
    }
    __syncthreads();

    // As2 = M @ s2
    for (int i = t; i < 1024; i += 256) {
        int a = i >> 4, c = i & 15;
        float acc = 0.f;
        for (int b = 0; b < 64; b++) acc += Ms[a*64 + b] * s2S[b*16 + c];
        As2[i] = acc;
    }
    __syncthreads();

    // pa2 = s2^T As2 ; sts2 = s2^T s2
    {
        int p = t >> 4, q = t & 15;
        float a1 = 0.f, a2 = 0.f;
        for (int a = 0; a < 64; a++) {
            float sp = s2S[a*16 + p];
            a1 += sp * As2[a*16 + q];
            a2 += sp * s2S[a*16 + q];
        }
        pa2[t] = a1; sts2[t] = a2;
    }
    __syncthreads();

    float tr2 = k6_sum((t < 16) ? pa2[t*17] : 0.f, redw, scal);
    float dv = 0.f;
    if (t < 64) {
        float q2 = 0.f;
        for (int c = 0; c < 16; c++) { float u = s2S[t*16 + c]; q2 += u*u; }
        dv = deg2[t] * q2;
    }
    float den2 = k6_sum(dv, redw, scal) + 1e-10f;
    float mc2 = -tr2 / den2;

    float f2 = sts2[t] * sts2[t];
    float norm2 = sqrtf(k6_sum(f2, redw, scal));
    float u2 = sts2[t] / (norm2 + 1e-10f) - (((t >> 4) == (t & 15)) ? 0.25f : 0.f);
    float o2 = sqrtf(k6_sum(u2*u2, redw, scal));

    if (t == 0) { out[0] = mc1; out[1] = o1; out[2] = mc2; out[3] = o2; }
}

// ---------------- launch ----------------
extern "C" void kernel_launch(void* const* d_in, const int* in_sizes, int n_in,
                              void* d_out, int out_size) {
    const float* x      = (const float*)d_in[0];
    const int*   ei     = (const int*)  d_in[1];
    const float* dm     = (const float*)d_in[2];
    const float* W1rel  = (const float*)d_in[3];
    const float* b1     = (const float*)d_in[4];
    const float* W1root = (const float*)d_in[5];
    const float* pW1    = (const float*)d_in[6];
    const float* pb1    = (const float*)d_in[7];
    const float* g1     = (const float*)d_in[8];
    const float* be1    = (const float*)d_in[9];
    const float* W2rel  = (const float*)d_in[10];
    const float* b2     = (const float*)d_in[11];
    const float* W2root = (const float*)d_in[12];
    const float* pW2    = (const float*)d_in[13];
    const float* pb2    = (const float*)d_in[14];
    const float* g2     = (const float*)d_in[15];
    const float* be2    = (const float*)d_in[16];
    float* out = (float*)d_out;
    const int* row = ei;
    const int* col = ei + EE;

    cudaFuncSetAttribute(kA, cudaFuncAttributeMaxDynamicSharedMemorySize, KA_SMEM_BYTES);
    cudaFuncSetAttribute(kB, cudaFuncAttributeMaxDynamicSharedMemorySize, KB_SMEM_BYTES);
    cudaFuncSetAttribute(k6, cudaFuncAttributeMaxDynamicSharedMemorySize, K6_SMEM_BYTES);

    int nblk = (NN + 63) / 64;  // 782

    kzero<<<512, 256>>>();
    kprep<<<64, 256>>>(W1rel, W1root, pW1);
    kscatter1<<<4096, 256>>>(x, dm, row, col);
    kA<<<nblk, 128, KA_SMEM_BYTES>>>(x, dm, b1);
    kB<<<nblk, 128, KB_SMEM_BYTES>>>(pb1, g1, be1, out + 4);
    kscatter2<<<4096, 256>>>(row, col);
    k5<<<296, 256>>>();
    k6<<<1, 256, K6_SMEM_BYTES>>>(W2rel, b2, W2root, pW2, pb2, g2, be2, out, out + 4 + (size_t)NN*C1N);
}